// round 9
// baseline (speedup 1.0000x reference)
#include <cuda_runtime.h>
#include <math.h>

#define BATCH 8
#define HW    262144   // 512*512 = 1<<18
#define SPIX  256
#define FEAT  64
#define NSEG  (BATCH * SPIX)   // 2048
#define BPB   92               // partial-blocks per batch (grid 736 = ~5 blocks/SM)
#define CHUNK 2850             // ceil(HW / BPB)
#define NBLK  (BATCH * BPB)    // 736
#define PSTR  12               // partial stride (10 moments + 2 pad -> 16B aligned)

// Static scratch (allocation-free, atomic-free pipeline):
// per-block partial moments [block][label][PSTR] and normalized reduced feats.
__device__ __align__(16) float g_part[NBLK * SPIX * PSTR];   // ~9 MB
__device__ float g_rn[NSEG * FEAT];

// ---------------------------------------------------------------------------
// Kernel 1: per-block moment accumulation in warp-private SMEM tables,
// software-pipelined (next trip's loads overlap current trip's match/RMW).
// Moment order: {n, sx0, sx1, sx2, s00, s01, s02, s11, s12, s22}
// ---------------------------------------------------------------------------
__global__ void __launch_bounds__(128) moments_kernel(const float* __restrict__ x,
                                                      const int* __restrict__ lab) {
    __shared__ float tbl[4][SPIX * 11];    // stride 11 (odd) -> conflict-light RMW
    const int tid = threadIdx.x, w = tid >> 5, lane = tid & 31;

    for (int i = tid; i < 4 * SPIX * 11; i += 128) ((float*)tbl)[i] = 0.0f;
    __syncthreads();

    const int b = blockIdx.x / BPB, c = blockIdx.x % BPB;
    const int start = c * CHUNK;
    const int end = min(start + CHUNK, HW);
    const float* __restrict__ xb = x + (size_t)b * 3 * HW;
    const int* __restrict__ lb = lab + (size_t)b * HW;
    float* const mytbl = tbl[w];

    const int ntrip = (end - start + 127) >> 7;

    // prologue: prefetch trip 0
    int i = start + tid;
    {
        bool v = i < end;
        int idx = v ? i : start;
        // fallthrough values loaded below in-loop pattern
    }
    bool v = i < end;
    int idx = v ? i : start;
    float x0 = xb[idx];
    float x1 = xb[idx + HW];
    float x2 = xb[idx + 2 * HW];
    int lbl = v ? (lb[idx] & (SPIX - 1)) : SPIX;

    for (int it = 0; it < ntrip; it++) {
        // ---- prefetch trip it+1 (overlaps everything below) ----
        int ni = i + 128;
        bool nv = ni < end;
        int nidx = nv ? ni : start;
        float nx0 = xb[nidx];
        float nx1 = xb[nidx + HW];
        float nx2 = xb[nidx + 2 * HW];
        int nlbl = nv ? (lb[nidx] & (SPIX - 1)) : SPIX;

        // ---- process current trip ----
        unsigned mm = __match_any_sync(0xffffffffu, lbl);
        int leader = __ffs(mm) - 1;
        float s0 = (float)__popc(mm);
        float s1 = x0, s2 = x1, s3 = x2;
        float s4 = x0 * x0, s5 = x0 * x1, s6 = x0 * x2;
        float s7 = x1 * x1, s8 = x1 * x2, s9 = x2 * x2;

        unsigned rem = mm & (mm - 1);   // group members minus leader
        while (__any_sync(0xffffffffu, rem != 0u)) {
            int src = rem ? (__ffs(rem) - 1) : 0;
            float t0 = __shfl_sync(0xffffffffu, x0, src);
            float t1 = __shfl_sync(0xffffffffu, x1, src);
            float t2 = __shfl_sync(0xffffffffu, x2, src);
            if (rem) {
                s1 += t0; s2 += t1; s3 += t2;
                s4 += t0 * t0; s5 += t0 * t1; s6 += t0 * t2;
                s7 += t1 * t1; s8 += t1 * t2; s9 += t2 * t2;
                rem &= rem - 1;
            }
        }
        if (lane == leader && lbl < SPIX) {
            float* t = mytbl + lbl * 11;
            t[0] += s0; t[1] += s1; t[2] += s2; t[3] += s3; t[4] += s4;
            t[5] += s5; t[6] += s6; t[7] += s7; t[8] += s8; t[9] += s9;
        }

        // rotate pipeline registers
        i = ni; x0 = nx0; x1 = nx1; x2 = nx2; lbl = nlbl;
    }
    __syncthreads();

    // flush: combine 4 warp tables -> dense per-block partial (plain stores)
    for (int l = tid; l < SPIX; l += 128) {
        float* dst = g_part + ((size_t)blockIdx.x * SPIX + l) * PSTR;
#pragma unroll
        for (int j = 0; j < 10; j++) {
            dst[j] = tbl[0][l * 11 + j] + tbl[1][l * 11 + j]
                   + tbl[2][l * 11 + j] + tbl[3][l * 11 + j];
        }
    }
}

// ---------------------------------------------------------------------------
// Kernel 2 (fused): partial-sum -> mean/std -> W_red matvec -> L2 normalize.
// 256 blocks x 256 threads; warp w handles seg = blk*8 + w.
// ---------------------------------------------------------------------------
__global__ void stats_kernel(const float* __restrict__ W_pix,
                             const float* __restrict__ b_pix,
                             const float* __restrict__ W_red,
                             const float* __restrict__ b_red) {
    __shared__ float s_wt[128 * 64];    // W_red transposed: [g][f]
    __shared__ float s_comb[8][128];    // per-warp combined [mean;std]

    int tid = threadIdx.x;
    for (int idx = tid; idx < 8192; idx += 256) {
        int f = idx >> 7, g = idx & 127;
        s_wt[g * 64 + f] = W_red[idx];  // coalesced read, transposed store
    }
    __syncthreads();

    int w = tid >> 5, lane = tid & 31;
    int seg = blockIdx.x * 8 + w;
    int b = seg >> 8, s = seg & (SPIX - 1);

    // ---- Phase A: sum the BPB per-block partials for this segment ----
    float mom[10];
#pragma unroll
    for (int j = 0; j < 10; j++) mom[j] = 0.0f;
    for (int blk = lane; blk < BPB; blk += 32) {
        const float4* pp = (const float4*)(g_part +
            ((size_t)(b * BPB + blk) * SPIX + s) * PSTR);
        float4 A = pp[0], B4 = pp[1], C4 = pp[2];
        mom[0] += A.x;  mom[1] += A.y;  mom[2] += A.z;  mom[3] += A.w;
        mom[4] += B4.x; mom[5] += B4.y; mom[6] += B4.z; mom[7] += B4.w;
        mom[8] += C4.x; mom[9] += C4.y;
    }
#pragma unroll
    for (int o = 16; o > 0; o >>= 1)
#pragma unroll
        for (int j = 0; j < 10; j++) mom[j] += __shfl_xor_sync(0xffffffffu, mom[j], o);

    float cnt = mom[0];
    float inv = 1.0f / fmaxf(cnt, 1.0f);
    float cn  = cnt * inv;  // 1 if nonempty, 0 if empty (matches ref clamp)
    float mx0 = mom[1] * inv, mx1 = mom[2] * inv, mx2 = mom[3] * inv;
    float M00 = mom[4] * inv, M01 = mom[5] * inv, M02 = mom[6] * inv;
    float M11 = mom[7] * inv, M12 = mom[8] * inv, M22 = mom[9] * inv;

    // ---- Phase B: per-feature stats + matvec + normalize ----
#pragma unroll
    for (int c = 0; c < 2; c++) {
        int f = lane + c * 32;
        float w0 = W_pix[3 * f], w1 = W_pix[3 * f + 1], w2 = W_pix[3 * f + 2];
        float bpv = b_pix[f];
        float d = w0 * mx0 + w1 * mx1 + w2 * mx2;
        float q = w0 * w0 * M00 + w1 * w1 * M11 + w2 * w2 * M22
                + 2.0f * (w0 * w1 * M01 + w0 * w2 * M02 + w1 * w2 * M12);
        float mean = d + bpv * cn;
        float e2   = q + 2.0f * bpv * d + bpv * bpv * cn;
        float var  = e2 - mean * mean;
        float sd   = sqrtf(fmaxf(var, 1e-6f));
        s_comb[w][f]      = mean;
        s_comb[w][64 + f] = sd;
    }
    __syncwarp();

    float r0 = b_red[lane], r1 = b_red[lane + 32];
#pragma unroll 8
    for (int g = 0; g < 128; g++) {
        float cg = s_comb[w][g];              // broadcast
        r0 += s_wt[g * 64 + lane]      * cg;  // conflict-free (stride 1)
        r1 += s_wt[g * 64 + lane + 32] * cg;
    }

    float ss = r0 * r0 + r1 * r1;
#pragma unroll
    for (int o = 16; o > 0; o >>= 1) ss += __shfl_xor_sync(0xffffffffu, ss, o);
    float invn = 1.0f / fmaxf(sqrtf(ss), 1e-12f);

    float* out = g_rn + (size_t)seg * FEAT;
    out[lane]      = r0 * invn;
    out[lane + 32] = r1 * invn;
}

// ---------------------------------------------------------------------------
// Kernel 3: sim = rn @ rn^T, fused affine(conv1x1 + BN) + ReLU  (unchanged)
// 32x32 tile/block, 16x16 threads, 2x2 outputs/thread.
// ---------------------------------------------------------------------------
__global__ void sim_kernel(const float* __restrict__ w_sim,
                           const float* __restrict__ b_sim,
                           const float* __restrict__ gma,
                           const float* __restrict__ bta,
                           const float* __restrict__ mu,
                           const float* __restrict__ vr,
                           float* __restrict__ out) {
    __shared__ float sa[64][34];   // [k][i]
    __shared__ float sb[64][34];   // [k][j]
    int b = blockIdx.z, i0 = blockIdx.y * 32, j0 = blockIdx.x * 32;
    int tx = threadIdx.x, ty = threadIdx.y;       // 16 x 16
    int tid = ty * 16 + tx;

    for (int idx = tid; idx < 2048; idx += 256) {
        int row = idx >> 6, k = idx & 63;
        sa[k][row] = g_rn[((size_t)(b * SPIX + i0 + row)) * FEAT + k];
        sb[k][row] = g_rn[((size_t)(b * SPIX + j0 + row)) * FEAT + k];
    }
    __syncthreads();

    float a00 = 0.f, a01 = 0.f, a10 = 0.f, a11 = 0.f;
#pragma unroll 16
    for (int k = 0; k < 64; k++) {
        float2 av = *(const float2*)&sa[k][ty * 2];
        float2 bv = *(const float2*)&sb[k][tx * 2];
        a00 += av.x * bv.x;
        a01 += av.x * bv.y;
        a10 += av.y * bv.x;
        a11 += av.y * bv.y;
    }

    float istd = 1.0f / sqrtf(vr[0] + 1e-5f);
    float A = gma[0] * w_sim[0] * istd;
    float C = gma[0] * (b_sim[0] - mu[0]) * istd + bta[0];

    float2 v0, v1;
    v0.x = fmaxf(A * a00 + C, 0.0f);
    v0.y = fmaxf(A * a01 + C, 0.0f);
    v1.x = fmaxf(A * a10 + C, 0.0f);
    v1.y = fmaxf(A * a11 + C, 0.0f);
    size_t base = ((size_t)(b * SPIX + i0 + ty * 2)) * SPIX + j0 + tx * 2;
    *(float2*)&out[base]        = v0;
    *(float2*)&out[base + SPIX] = v1;
}

// ---------------------------------------------------------------------------
extern "C" void kernel_launch(void* const* d_in, const int* in_sizes, int n_in,
                              void* d_out, int out_size) {
    const float* x   = (const float*)d_in[0];
    const int*   lab = (const int*)d_in[1];
    // num_spixels may or may not appear as a size-1 input between labels and W_pix
    int o = (in_sizes[2] == 192) ? 2 : 3;
    const float* W_pix = (const float*)d_in[o];
    const float* b_pix = (const float*)d_in[o + 1];
    const float* W_red = (const float*)d_in[o + 2];
    const float* b_red = (const float*)d_in[o + 3];
    const float* w_sim = (const float*)d_in[o + 4];
    const float* b_sim = (const float*)d_in[o + 5];
    const float* gma   = (const float*)d_in[o + 6];
    const float* bta   = (const float*)d_in[o + 7];
    const float* mu    = (const float*)d_in[o + 8];
    const float* vr    = (const float*)d_in[o + 9];

    moments_kernel<<<NBLK, 128>>>(x, lab);
    stats_kernel<<<256, 256>>>(W_pix, b_pix, W_red, b_red);
    dim3 g3(8, 8, 8), b3(16, 16);
    sim_kernel<<<g3, b3>>>(w_sim, b_sim, gma, bta, mu, vr, (float*)d_out);
}

// round 11
// speedup vs baseline: 1.0719x; 1.0719x over previous
#include <cuda_runtime.h>
#include <math.h>

#define BATCH 8
#define HW    262144   // 512*512 = 1<<18
#define SPIX  256
#define FEAT  64
#define NSEG  (BATCH * SPIX)   // 2048
#define BPB   74               // partial-blocks per batch (grid 592 = 4 blocks/SM)
#define CHUNK 3543             // ceil(HW / BPB)
#define NBLK  (BATCH * BPB)    // 592
#define PSTR  12               // stride: 10 moments + 2 pad -> three float4s

// Static scratch (allocation-free, atomic-free pipeline):
// per-block partial moments [block][label][PSTR] and normalized reduced feats.
__device__ __align__(16) float g_part[NBLK * SPIX * PSTR];   // ~7.3 MB
__device__ float g_rn[NSEG * FEAT];

// ---------------------------------------------------------------------------
// Kernel 1: per-block moment accumulation in warp-private SMEM tables.
// Software-pipelined loads; table RMW via 128-bit LDS/STS (stride 12).
// Moment order: {n, sx0, sx1, sx2 | s00, s01, s02, s11 | s12, s22, pad, pad}
// ---------------------------------------------------------------------------
__global__ void __launch_bounds__(128) moments_kernel(const float* __restrict__ x,
                                                      const int* __restrict__ lab) {
    __shared__ __align__(16) float tbl[4][SPIX * 12];   // 48 KB
    const int tid = threadIdx.x, w = tid >> 5, lane = tid & 31;

    for (int i = tid; i < 4 * SPIX * 12 / 4; i += 128)
        ((float4*)tbl)[i] = make_float4(0.f, 0.f, 0.f, 0.f);
    __syncthreads();

    const int b = blockIdx.x / BPB, c = blockIdx.x % BPB;
    const int start = c * CHUNK;
    const int end = min(start + CHUNK, HW);
    const float* __restrict__ xb = x + (size_t)b * 3 * HW;
    const int* __restrict__ lb = lab + (size_t)b * HW;
    float* const mytbl = tbl[w];

    const int ntrip = (end - start + 127) >> 7;

    // prologue: prefetch trip 0
    int i = start + tid;
    bool v = i < end;
    int idx = v ? i : start;
    float x0 = xb[idx];
    float x1 = xb[idx + HW];
    float x2 = xb[idx + 2 * HW];
    int lbl = v ? (lb[idx] & (SPIX - 1)) : SPIX;

    for (int it = 0; it < ntrip; it++) {
        // ---- prefetch trip it+1 (overlaps everything below) ----
        int ni = i + 128;
        bool nv = ni < end;
        int nidx = nv ? ni : start;
        float nx0 = xb[nidx];
        float nx1 = xb[nidx + HW];
        float nx2 = xb[nidx + 2 * HW];
        int nlbl = nv ? (lb[nidx] & (SPIX - 1)) : SPIX;

        // ---- process current trip ----
        unsigned mm = __match_any_sync(0xffffffffu, lbl);
        int leader = __ffs(mm) - 1;
        float s0 = (float)__popc(mm);
        float s1 = x0, s2 = x1, s3 = x2;
        float s4 = x0 * x0, s5 = x0 * x1, s6 = x0 * x2;
        float s7 = x1 * x1, s8 = x1 * x2, s9 = x2 * x2;

        unsigned rem = mm & (mm - 1);   // group members minus leader
        while (__any_sync(0xffffffffu, rem != 0u)) {
            int src = rem ? (__ffs(rem) - 1) : 0;
            float t0 = __shfl_sync(0xffffffffu, x0, src);
            float t1 = __shfl_sync(0xffffffffu, x1, src);
            float t2 = __shfl_sync(0xffffffffu, x2, src);
            if (rem) {
                s1 += t0; s2 += t1; s3 += t2;
                s4 += t0 * t0; s5 += t0 * t1; s6 += t0 * t2;
                s7 += t1 * t1; s8 += t1 * t2; s9 += t2 * t2;
                rem &= rem - 1;
            }
        }
        if (lane == leader && lbl < SPIX) {
            float4* t = (float4*)(mytbl + lbl * 12);
            float4 a = t[0], bq = t[1], cq = t[2];
            a.x += s0;  a.y += s1;  a.z += s2;  a.w += s3;
            bq.x += s4; bq.y += s5; bq.z += s6; bq.w += s7;
            cq.x += s8; cq.y += s9;
            t[0] = a; t[1] = bq; t[2] = cq;
        }

        // rotate pipeline registers
        i = ni; x0 = nx0; x1 = nx1; x2 = nx2; lbl = nlbl;
    }
    __syncthreads();

    // flush: combine 4 warp tables -> dense per-block partial (float4 stores)
    for (int l = tid; l < SPIX; l += 128) {
        float4* dst = (float4*)(g_part + ((size_t)blockIdx.x * SPIX + l) * PSTR);
#pragma unroll
        for (int q = 0; q < 3; q++) {
            float4 a = ((float4*)(tbl[0] + l * 12))[q];
            float4 bq = ((float4*)(tbl[1] + l * 12))[q];
            float4 cq = ((float4*)(tbl[2] + l * 12))[q];
            float4 dq = ((float4*)(tbl[3] + l * 12))[q];
            float4 r;
            r.x = a.x + bq.x + cq.x + dq.x;
            r.y = a.y + bq.y + cq.y + dq.y;
            r.z = a.z + bq.z + cq.z + dq.z;
            r.w = a.w + bq.w + cq.w + dq.w;
            dst[q] = r;
        }
    }
}

// ---------------------------------------------------------------------------
// Kernel 2 (fused): partial-sum -> mean/std -> W_red matvec -> L2 normalize.
// 256 blocks x 256 threads; warp w handles seg = blk*8 + w.
// ---------------------------------------------------------------------------
__global__ void stats_kernel(const float* __restrict__ W_pix,
                             const float* __restrict__ b_pix,
                             const float* __restrict__ W_red,
                             const float* __restrict__ b_red) {
    __shared__ float s_wt[128 * 64];    // W_red transposed: [g][f]
    __shared__ float s_comb[8][128];    // per-warp combined [mean;std]

    int tid = threadIdx.x;
    for (int idx = tid; idx < 8192; idx += 256) {
        int f = idx >> 7, g = idx & 127;
        s_wt[g * 64 + f] = W_red[idx];  // coalesced read, transposed store
    }
    __syncthreads();

    int w = tid >> 5, lane = tid & 31;
    int seg = blockIdx.x * 8 + w;
    int b = seg >> 8, s = seg & (SPIX - 1);

    // ---- Phase A: sum the BPB per-block partials for this segment ----
    float mom[10];
#pragma unroll
    for (int j = 0; j < 10; j++) mom[j] = 0.0f;
    for (int blk = lane; blk < BPB; blk += 32) {
        const float4* pp = (const float4*)(g_part +
            ((size_t)(b * BPB + blk) * SPIX + s) * PSTR);
        float4 A = pp[0], B4 = pp[1], C4 = pp[2];
        mom[0] += A.x;  mom[1] += A.y;  mom[2] += A.z;  mom[3] += A.w;
        mom[4] += B4.x; mom[5] += B4.y; mom[6] += B4.z; mom[7] += B4.w;
        mom[8] += C4.x; mom[9] += C4.y;
    }
#pragma unroll
    for (int o = 16; o > 0; o >>= 1)
#pragma unroll
        for (int j = 0; j < 10; j++) mom[j] += __shfl_xor_sync(0xffffffffu, mom[j], o);

    float cnt = mom[0];
    float inv = 1.0f / fmaxf(cnt, 1.0f);
    float cn  = cnt * inv;  // 1 if nonempty, 0 if empty (matches ref clamp)
    float mx0 = mom[1] * inv, mx1 = mom[2] * inv, mx2 = mom[3] * inv;
    float M00 = mom[4] * inv, M01 = mom[5] * inv, M02 = mom[6] * inv;
    float M11 = mom[7] * inv, M12 = mom[8] * inv, M22 = mom[9] * inv;

    // ---- Phase B: per-feature stats + matvec + normalize ----
#pragma unroll
    for (int c = 0; c < 2; c++) {
        int f = lane + c * 32;
        float w0 = W_pix[3 * f], w1 = W_pix[3 * f + 1], w2 = W_pix[3 * f + 2];
        float bpv = b_pix[f];
        float d = w0 * mx0 + w1 * mx1 + w2 * mx2;
        float q = w0 * w0 * M00 + w1 * w1 * M11 + w2 * w2 * M22
                + 2.0f * (w0 * w1 * M01 + w0 * w2 * M02 + w1 * w2 * M12);
        float mean = d + bpv * cn;
        float e2   = q + 2.0f * bpv * d + bpv * bpv * cn;
        float var  = e2 - mean * mean;
        float sd   = sqrtf(fmaxf(var, 1e-6f));
        s_comb[w][f]      = mean;
        s_comb[w][64 + f] = sd;
    }
    __syncwarp();

    float r0 = b_red[lane], r1 = b_red[lane + 32];
#pragma unroll 8
    for (int g = 0; g < 128; g++) {
        float cg = s_comb[w][g];              // broadcast
        r0 += s_wt[g * 64 + lane]      * cg;  // conflict-free (stride 1)
        r1 += s_wt[g * 64 + lane + 32] * cg;
    }

    float ss = r0 * r0 + r1 * r1;
#pragma unroll
    for (int o = 16; o > 0; o >>= 1) ss += __shfl_xor_sync(0xffffffffu, ss, o);
    float invn = 1.0f / fmaxf(sqrtf(ss), 1e-12f);

    float* out = g_rn + (size_t)seg * FEAT;
    out[lane]      = r0 * invn;
    out[lane + 32] = r1 * invn;
}

// ---------------------------------------------------------------------------
// Kernel 3: sim = rn @ rn^T, fused affine(conv1x1 + BN) + ReLU  (unchanged)
// 32x32 tile/block, 16x16 threads, 2x2 outputs/thread.
// ---------------------------------------------------------------------------
__global__ void sim_kernel(const float* __restrict__ w_sim,
                           const float* __restrict__ b_sim,
                           const float* __restrict__ gma,
                           const float* __restrict__ bta,
                           const float* __restrict__ mu,
                           const float* __restrict__ vr,
                           float* __restrict__ out) {
    __shared__ float sa[64][34];   // [k][i]
    __shared__ float sb[64][34];   // [k][j]
    int b = blockIdx.z, i0 = blockIdx.y * 32, j0 = blockIdx.x * 32;
    int tx = threadIdx.x, ty = threadIdx.y;       // 16 x 16
    int tid = ty * 16 + tx;

    for (int idx = tid; idx < 2048; idx += 256) {
        int row = idx >> 6, k = idx & 63;
        sa[k][row] = g_rn[((size_t)(b * SPIX + i0 + row)) * FEAT + k];
        sb[k][row] = g_rn[((size_t)(b * SPIX + j0 + row)) * FEAT + k];
    }
    __syncthreads();

    float a00 = 0.f, a01 = 0.f, a10 = 0.f, a11 = 0.f;
#pragma unroll 16
    for (int k = 0; k < 64; k++) {
        float2 av = *(const float2*)&sa[k][ty * 2];
        float2 bv = *(const float2*)&sb[k][tx * 2];
        a00 += av.x * bv.x;
        a01 += av.x * bv.y;
        a10 += av.y * bv.x;
        a11 += av.y * bv.y;
    }

    float istd = 1.0f / sqrtf(vr[0] + 1e-5f);
    float A = gma[0] * w_sim[0] * istd;
    float C = gma[0] * (b_sim[0] - mu[0]) * istd + bta[0];

    float2 v0, v1;
    v0.x = fmaxf(A * a00 + C, 0.0f);
    v0.y = fmaxf(A * a01 + C, 0.0f);
    v1.x = fmaxf(A * a10 + C, 0.0f);
    v1.y = fmaxf(A * a11 + C, 0.0f);
    size_t base = ((size_t)(b * SPIX + i0 + ty * 2)) * SPIX + j0 + tx * 2;
    *(float2*)&out[base]        = v0;
    *(float2*)&out[base + SPIX] = v1;
}

// ---------------------------------------------------------------------------
extern "C" void kernel_launch(void* const* d_in, const int* in_sizes, int n_in,
                              void* d_out, int out_size) {
    const float* x   = (const float*)d_in[0];
    const int*   lab = (const int*)d_in[1];
    // num_spixels may or may not appear as a size-1 input between labels and W_pix
    int o = (in_sizes[2] == 192) ? 2 : 3;
    const float* W_pix = (const float*)d_in[o];
    const float* b_pix = (const float*)d_in[o + 1];
    const float* W_red = (const float*)d_in[o + 2];
    const float* b_red = (const float*)d_in[o + 3];
    const float* w_sim = (const float*)d_in[o + 4];
    const float* b_sim = (const float*)d_in[o + 5];
    const float* gma   = (const float*)d_in[o + 6];
    const float* bta   = (const float*)d_in[o + 7];
    const float* mu    = (const float*)d_in[o + 8];
    const float* vr    = (const float*)d_in[o + 9];

    moments_kernel<<<NBLK, 128>>>(x, lab);
    stats_kernel<<<256, 256>>>(W_pix, b_pix, W_red, b_red);
    dim3 g3(8, 8, 8), b3(16, 16);
    sim_kernel<<<g3, b3>>>(w_sim, b_sim, gma, bta, mu, vr, (float*)d_out);
}